// round 9
// baseline (speedup 1.0000x reference)
#include <cuda_runtime.h>

// hidden [4096] f32, encoder_outputs [8192,1,4096] f32
// energies = enc @ hidden -> softmax -> output = enc^T @ attn
// d_out: [0:4096) = output, [4096:12288) = attn
//
// pass1: 4 rows/block in registers, ONE hot-path syncthreads, block-local
//        softmax, partial spill; last block computes global stats + weights.
// combine: weighted reduction of partials (full width) + attn write.

#define SEQ_LEN 8192
#define HIDDEN  4096
#define H4      (HIDDEN / 4)
#define NBLK    2048
#define ROWS    4                  // rows per pass1 block
#define BCHUNK  8                  // partial rows folded per combine block
#define NOUTB   (NBLK / BCHUNK)    // 256 combine blocks for out

__device__ float g_energies[SEQ_LEN];
__device__ float g_partial[(size_t)NBLK * HIDDEN];
__device__ float g_m[NBLK];
__device__ float g_l[NBLK];
__device__ float g_w[NBLK];        // exp(m_b - M) / Z
__device__ float g_stats[2];       // {M, invZ}
__device__ int   g_count;          // zero-init; reset by finalizer each launch

// ---------------------------------------------------------------------------
__global__ __launch_bounds__(256, 2) void pass1(
    const float* __restrict__ enc, const float* __restrict__ hidden,
    float* __restrict__ out)
{
    const int tid  = threadIdx.x;
    const int wid  = tid >> 5;
    const int lane = tid & 31;
    const int r0   = blockIdx.x * ROWS;

    if (blockIdx.x < 16) out[blockIdx.x * 256 + tid] = 0.f;

    __shared__ float sred[ROWS][8];
    __shared__ int   s_last;

    const float4* h4 = reinterpret_cast<const float4*>(hidden);
    float4 hv0 = h4[tid];
    float4 hv1 = h4[tid + 256];
    float4 hv2 = h4[tid + 512];
    float4 hv3 = h4[tid + 768];

    // load 4 rows x 4 float4 into registers (16 independent loads)
    float4 d[ROWS][4];
    #pragma unroll
    for (int s = 0; s < ROWS; ++s) {
        const float4* b = reinterpret_cast<const float4*>(enc + (size_t)(r0 + s) * HIDDEN);
        d[s][0] = b[tid];
        d[s][1] = b[tid + 256];
        d[s][2] = b[tid + 512];
        d[s][3] = b[tid + 768];
    }

    // 4 dot partials in parallel
    float dot[ROWS];
    #pragma unroll
    for (int s = 0; s < ROWS; ++s) {
        dot[s] = d[s][0].x*hv0.x + d[s][0].y*hv0.y + d[s][0].z*hv0.z + d[s][0].w*hv0.w
               + d[s][1].x*hv1.x + d[s][1].y*hv1.y + d[s][1].z*hv1.z + d[s][1].w*hv1.w
               + d[s][2].x*hv2.x + d[s][2].y*hv2.y + d[s][2].z*hv2.z + d[s][2].w*hv2.w
               + d[s][3].x*hv3.x + d[s][3].y*hv3.y + d[s][3].z*hv3.z + d[s][3].w*hv3.w;
    }
    #pragma unroll
    for (int off = 16; off > 0; off >>= 1) {
        #pragma unroll
        for (int s = 0; s < ROWS; ++s)
            dot[s] += __shfl_down_sync(0xFFFFFFFFu, dot[s], off);
    }
    if (lane == 0) {
        #pragma unroll
        for (int s = 0; s < ROWS; ++s) sred[s][wid] = dot[s];
    }
    __syncthreads();   // the ONLY hot-path block sync

    float e[ROWS];
    #pragma unroll
    for (int s = 0; s < ROWS; ++s)
        e[s] = sred[s][0] + sred[s][1] + sred[s][2] + sred[s][3]
             + sred[s][4] + sred[s][5] + sred[s][6] + sred[s][7];

    // block-local softmax weights
    float m = fmaxf(fmaxf(e[0], e[1]), fmaxf(e[2], e[3]));
    float p[ROWS], l = 0.f;
    #pragma unroll
    for (int s = 0; s < ROWS; ++s) { p[s] = __expf(e[s] - m); l += p[s]; }

    // weighted accumulation in registers
    float4 acc[4];
    #pragma unroll
    for (int k = 0; k < 4; ++k) acc[k] = make_float4(0.f, 0.f, 0.f, 0.f);
    #pragma unroll
    for (int s = 0; s < ROWS; ++s) {
        #pragma unroll
        for (int k = 0; k < 4; ++k) {
            acc[k].x += p[s] * d[s][k].x;
            acc[k].y += p[s] * d[s][k].y;
            acc[k].z += p[s] * d[s][k].z;
            acc[k].w += p[s] * d[s][k].w;
        }
    }

    float4* gp = reinterpret_cast<float4*>(g_partial + (size_t)blockIdx.x * HIDDEN);
    gp[tid]       = acc[0];
    gp[tid + 256] = acc[1];
    gp[tid + 512] = acc[2];
    gp[tid + 768] = acc[3];
    if (tid == 0) { g_m[blockIdx.x] = m; g_l[blockIdx.x] = l; }
    if (tid < ROWS) g_energies[r0 + tid] = e[tid];

    // ---- last-arriving block computes global stats + weights ----
    __threadfence();
    __syncthreads();
    if (tid == 0) {
        int t = atomicAdd(&g_count, 1);
        s_last = (t == NBLK - 1);
    }
    __syncthreads();
    if (!s_last) return;

    __shared__ float red2[8];
    __shared__ float sM, sZ;

    float mb[8];
    float mv = -3.4e38f;
    #pragma unroll
    for (int k = 0; k < 8; ++k) {
        mb[k] = g_m[tid + k * 256];
        mv = fmaxf(mv, mb[k]);
    }
    #pragma unroll
    for (int off = 16; off > 0; off >>= 1)
        mv = fmaxf(mv, __shfl_xor_sync(0xFFFFFFFFu, mv, off));
    if (lane == 0) red2[wid] = mv;
    __syncthreads();
    if (tid == 0) {
        float v = red2[0];
        #pragma unroll
        for (int i = 1; i < 8; ++i) v = fmaxf(v, red2[i]);
        sM = v;
    }
    __syncthreads();
    float M = sM;

    float zt = 0.f;
    #pragma unroll
    for (int k = 0; k < 8; ++k)
        zt += g_l[tid + k * 256] * __expf(mb[k] - M);
    #pragma unroll
    for (int off = 16; off > 0; off >>= 1)
        zt += __shfl_xor_sync(0xFFFFFFFFu, zt, off);
    if (lane == 0) red2[wid] = zt;
    __syncthreads();
    if (tid == 0) {
        float v = red2[0];
        #pragma unroll
        for (int i = 1; i < 8; ++i) v += red2[i];
        sZ = v;
    }
    __syncthreads();
    float invZ = 1.0f / sZ;

    #pragma unroll
    for (int k = 0; k < 8; ++k)
        g_w[tid + k * 256] = __expf(mb[k] - M) * invZ;
    if (tid == 0) { g_stats[0] = M; g_stats[1] = invZ; g_count = 0; }
}

// ---------------------------------------------------------------------------
// combine: blocks [0,NOUTB) fold 8 partial rows (FULL 4096 width) into out;
//          blocks [NOUTB, NOUTB+32) write attn.
__global__ __launch_bounds__(256) void combine(
    float* __restrict__ out, float* __restrict__ attn)
{
    const int tid = threadIdx.x;
    const int gid = blockIdx.x;

    if (gid < NOUTB) {
        __shared__ float w[BCHUNK];
        const int b0 = gid * BCHUNK;
        if (tid < BCHUNK) w[tid] = g_w[b0 + tid];
        __syncthreads();

        float4 acc0 = make_float4(0.f,0.f,0.f,0.f);
        float4 acc1 = acc0, acc2 = acc0, acc3 = acc0;
        const float4* gp = reinterpret_cast<const float4*>(g_partial) + (size_t)b0 * H4;
        #pragma unroll
        for (int j = 0; j < BCHUNK; ++j) {
            const float4* row = gp + (size_t)j * H4;
            float ww = w[j];
            float4 v0 = row[tid];
            float4 v1 = row[tid + 256];
            float4 v2 = row[tid + 512];
            float4 v3 = row[tid + 768];
            acc0.x += ww*v0.x; acc0.y += ww*v0.y; acc0.z += ww*v0.z; acc0.w += ww*v0.w;
            acc1.x += ww*v1.x; acc1.y += ww*v1.y; acc1.z += ww*v1.z; acc1.w += ww*v1.w;
            acc2.x += ww*v2.x; acc2.y += ww*v2.y; acc2.z += ww*v2.z; acc2.w += ww*v2.w;
            acc3.x += ww*v3.x; acc3.y += ww*v3.y; acc3.z += ww*v3.z; acc3.w += ww*v3.w;
        }
        atomicAdd(&out[tid*4 + 0],        acc0.x);
        atomicAdd(&out[tid*4 + 1],        acc0.y);
        atomicAdd(&out[tid*4 + 2],        acc0.z);
        atomicAdd(&out[tid*4 + 3],        acc0.w);
        atomicAdd(&out[1024 + tid*4 + 0], acc1.x);
        atomicAdd(&out[1024 + tid*4 + 1], acc1.y);
        atomicAdd(&out[1024 + tid*4 + 2], acc1.z);
        atomicAdd(&out[1024 + tid*4 + 3], acc1.w);
        atomicAdd(&out[2048 + tid*4 + 0], acc2.x);
        atomicAdd(&out[2048 + tid*4 + 1], acc2.y);
        atomicAdd(&out[2048 + tid*4 + 2], acc2.z);
        atomicAdd(&out[2048 + tid*4 + 3], acc2.w);
        atomicAdd(&out[3072 + tid*4 + 0], acc3.x);
        atomicAdd(&out[3072 + tid*4 + 1], acc3.y);
        atomicAdd(&out[3072 + tid*4 + 2], acc3.z);
        atomicAdd(&out[3072 + tid*4 + 3], acc3.w);
    } else {
        const float M    = g_stats[0];
        const float invZ = g_stats[1];
        const int i = (gid - NOUTB) * 256 + tid;
        attn[i] = __expf(g_energies[i] - M) * invZ;
    }
}

extern "C" void kernel_launch(void* const* d_in, const int* in_sizes, int n_in,
                              void* d_out, int out_size)
{
    const float* hidden = (const float*)d_in[0];
    const float* enc    = (const float*)d_in[1];
    float* out  = (float*)d_out;
    float* attn = (float*)d_out + HIDDEN;

    pass1<<<NBLK, 256>>>(enc, hidden, out);
    combine<<<NOUTB + SEQ_LEN / 256, 256>>>(out, attn);
}

// round 10
// speedup vs baseline: 1.6547x; 1.6547x over previous
#include <cuda_runtime.h>

// hidden [4096] f32, encoder_outputs [8192,1,4096] f32
// energies = enc @ hidden -> softmax -> output = enc^T @ attn
// d_out: [0:4096) = output, [4096:12288) = attn
//
// pass1: 512 blocks x 16 rows, processed as 4 groups of 4 rows (16 loads in
//        flight per group, one rescale per group). Last block finalizes stats.
// combine: 16 col-groups x 32 b-chunks, 32 atomics/address max.

#define SEQ_LEN 8192
#define HIDDEN  4096
#define H4      (HIDDEN / 4)
#define NBLK    512
#define ROWS    16                 // rows per pass1 block
#define GRP     4                  // rows per inner group
#define NGRP    (ROWS / GRP)       // 4
#define BCHUNK  16                 // partial rows per combine block
#define NBCH    (NBLK / BCHUNK)    // 32

__device__ float g_energies[SEQ_LEN];
__device__ float g_partial[(size_t)NBLK * HIDDEN];
__device__ float g_m[NBLK];
__device__ float g_l[NBLK];
__device__ float g_w[NBLK];        // exp(m_b - M) / Z
__device__ float g_stats[2];       // {M, invZ}
__device__ int   g_count;          // zero-init; reset by finalizer each launch

// ---------------------------------------------------------------------------
__global__ __launch_bounds__(256, 2) void pass1(
    const float* __restrict__ enc, const float* __restrict__ hidden,
    float* __restrict__ out)
{
    const int tid  = threadIdx.x;
    const int wid  = tid >> 5;
    const int lane = tid & 31;
    const int r0   = blockIdx.x * ROWS;

    if (blockIdx.x < 16) out[blockIdx.x * 256 + tid] = 0.f;

    __shared__ float sred[2][GRP][8];
    __shared__ int   s_last;

    const float4* h4 = reinterpret_cast<const float4*>(hidden);
    float4 hv0 = h4[tid];
    float4 hv1 = h4[tid + 256];
    float4 hv2 = h4[tid + 512];
    float4 hv3 = h4[tid + 768];

    float4 acc[4];
    #pragma unroll
    for (int k = 0; k < 4; ++k) acc[k] = make_float4(0.f, 0.f, 0.f, 0.f);
    float m = -3.4e38f;
    float l = 0.f;

    #pragma unroll 1
    for (int g = 0; g < NGRP; ++g) {
        const int rg = r0 + g * GRP;

        // 4 rows x 4 float4 = 16 independent loads, front-batched
        float4 d[GRP][4];
        #pragma unroll
        for (int s = 0; s < GRP; ++s) {
            const float4* b = reinterpret_cast<const float4*>(enc + (size_t)(rg + s) * HIDDEN);
            d[s][0] = b[tid];
            d[s][1] = b[tid + 256];
            d[s][2] = b[tid + 512];
            d[s][3] = b[tid + 768];
        }

        float dot[GRP];
        #pragma unroll
        for (int s = 0; s < GRP; ++s) {
            dot[s] = d[s][0].x*hv0.x + d[s][0].y*hv0.y + d[s][0].z*hv0.z + d[s][0].w*hv0.w
                   + d[s][1].x*hv1.x + d[s][1].y*hv1.y + d[s][1].z*hv1.z + d[s][1].w*hv1.w
                   + d[s][2].x*hv2.x + d[s][2].y*hv2.y + d[s][2].z*hv2.z + d[s][2].w*hv2.w
                   + d[s][3].x*hv3.x + d[s][3].y*hv3.y + d[s][3].z*hv3.z + d[s][3].w*hv3.w;
        }
        #pragma unroll
        for (int off = 16; off > 0; off >>= 1) {
            #pragma unroll
            for (int s = 0; s < GRP; ++s)
                dot[s] += __shfl_down_sync(0xFFFFFFFFu, dot[s], off);
        }
        if (lane == 0) {
            #pragma unroll
            for (int s = 0; s < GRP; ++s) sred[g & 1][s][wid] = dot[s];
        }
        __syncthreads();

        float e[GRP];
        #pragma unroll
        for (int s = 0; s < GRP; ++s)
            e[s] = sred[g & 1][s][0] + sred[g & 1][s][1] + sred[g & 1][s][2] + sred[g & 1][s][3]
                 + sred[g & 1][s][4] + sred[g & 1][s][5] + sred[g & 1][s][6] + sred[g & 1][s][7];
        if (tid < GRP) g_energies[rg + tid] = e[tid];

        // one online-rescale per group
        float mg = fmaxf(fmaxf(e[0], e[1]), fmaxf(e[2], e[3]));
        float mn = fmaxf(m, mg);
        float sc = __expf(m - mn);
        float p[GRP];
        float ps = 0.f;
        #pragma unroll
        for (int s = 0; s < GRP; ++s) { p[s] = __expf(e[s] - mn); ps += p[s]; }

        #pragma unroll
        for (int k = 0; k < 4; ++k) {
            acc[k].x *= sc; acc[k].y *= sc; acc[k].z *= sc; acc[k].w *= sc;
        }
        #pragma unroll
        for (int s = 0; s < GRP; ++s) {
            #pragma unroll
            for (int k = 0; k < 4; ++k) {
                acc[k].x += p[s] * d[s][k].x;
                acc[k].y += p[s] * d[s][k].y;
                acc[k].z += p[s] * d[s][k].z;
                acc[k].w += p[s] * d[s][k].w;
            }
        }
        l = l * sc + ps;
        m = mn;
    }

    float4* gp = reinterpret_cast<float4*>(g_partial + (size_t)blockIdx.x * HIDDEN);
    gp[tid]       = acc[0];
    gp[tid + 256] = acc[1];
    gp[tid + 512] = acc[2];
    gp[tid + 768] = acc[3];
    if (tid == 0) { g_m[blockIdx.x] = m; g_l[blockIdx.x] = l; }

    // ---- last-arriving block computes global stats + weights ----
    __threadfence();
    __syncthreads();
    if (tid == 0) {
        int t = atomicAdd(&g_count, 1);
        s_last = (t == NBLK - 1);
    }
    __syncthreads();
    if (!s_last) return;

    __shared__ float red2[8];
    __shared__ float sM, sZ;

    float mb0 = g_m[tid];
    float mb1 = g_m[tid + 256];
    float mv = fmaxf(mb0, mb1);
    #pragma unroll
    for (int off = 16; off > 0; off >>= 1)
        mv = fmaxf(mv, __shfl_xor_sync(0xFFFFFFFFu, mv, off));
    if (lane == 0) red2[wid] = mv;
    __syncthreads();
    if (tid == 0) {
        float v = red2[0];
        #pragma unroll
        for (int i = 1; i < 8; ++i) v = fmaxf(v, red2[i]);
        sM = v;
    }
    __syncthreads();
    float M = sM;

    float zt = g_l[tid] * __expf(mb0 - M) + g_l[tid + 256] * __expf(mb1 - M);
    #pragma unroll
    for (int off = 16; off > 0; off >>= 1)
        zt += __shfl_xor_sync(0xFFFFFFFFu, zt, off);
    if (lane == 0) red2[wid] = zt;
    __syncthreads();
    if (tid == 0) {
        float v = red2[0];
        #pragma unroll
        for (int i = 1; i < 8; ++i) v += red2[i];
        sZ = v;
    }
    __syncthreads();
    float invZ = 1.0f / sZ;

    g_w[tid]       = __expf(mb0 - M) * invZ;
    g_w[tid + 256] = __expf(mb1 - M) * invZ;
    if (tid == 0) { g_stats[0] = M; g_stats[1] = invZ; g_count = 0; }
}

// ---------------------------------------------------------------------------
// combine: blocks [0, 16*NBCH) : col-group x b-chunk partial fold (atomic);
//          blocks [16*NBCH, +32): attn write.
__global__ __launch_bounds__(256) void combine(
    float* __restrict__ out, float* __restrict__ attn)
{
    const int tid = threadIdx.x;
    const int gid = blockIdx.x;

    if (gid < 16 * NBCH) {
        __shared__ float w[BCHUNK];
        const int col = (gid & 15) * 256 + tid;
        const int b0  = (gid >> 4) * BCHUNK;
        if (tid < BCHUNK) w[tid] = g_w[b0 + tid];
        __syncthreads();

        float acc = 0.f;
        #pragma unroll
        for (int j = 0; j < BCHUNK; ++j)
            acc += g_partial[(size_t)(b0 + j) * HIDDEN + col] * w[j];
        atomicAdd(&out[col], acc);
    } else {
        const float M    = g_stats[0];
        const float invZ = g_stats[1];
        const int i = (gid - 16 * NBCH) * 256 + tid;
        attn[i] = __expf(g_energies[i] - M) * invZ;
    }
}

extern "C" void kernel_launch(void* const* d_in, const int* in_sizes, int n_in,
                              void* d_out, int out_size)
{
    const float* hidden = (const float*)d_in[0];
    const float* enc    = (const float*)d_in[1];
    float* out  = (float*)d_out;
    float* attn = (float*)d_out + HIDDEN;

    pass1<<<NBLK, 256>>>(enc, hidden, out);
    combine<<<16 * NBCH + SEQ_LEN / 256, 256>>>(out, attn);
}